// round 2
// baseline (speedup 1.0000x reference)
#include <cuda_runtime.h>

#define N_NODES 40000
#define N_EDGES 800000
#define IN_DIM  128
#define COM_DIM 128
#define N_ETYPE 5
#define N_HEADS 4
#define NCH     20            // N_HEADS * N_ETYPE
#define NEG_SLOPE 0.2f
#define TM 64                 // nodes per GEMM block

// ---------------- device scratch (no allocation allowed) ----------------
__device__ float g_mess[N_ETYPE * N_NODES * COM_DIM];   // 102.4 MB
__device__ float g_el[N_NODES * NCH];
__device__ float g_er[N_NODES * NCH];
__device__ int   g_deg[N_NODES];                         // degree, then cursor
__device__ int   g_rowptr[N_NODES + 1];
__device__ int   g_eidx[N_EDGES];

// ---------------- Phase 1: mess = mask * (feat @ W_t) + com ----------------
__global__ __launch_bounds__(256) void gemm_kernel(
    const float* __restrict__ feat, const float* __restrict__ com,
    const float* __restrict__ mask, const float* __restrict__ W)
{
    extern __shared__ float sh[];
    float* sW = sh;                        // [128][128]
    float* sF = sh + IN_DIM * COM_DIM;     // [128][TM]  (k-major, transposed feat)
    const int t  = blockIdx.y;
    const int n0 = blockIdx.x * TM;
    const int tid = threadIdx.x;

    const float* Wt = W + (size_t)t * IN_DIM * COM_DIM;
    for (int i = tid; i < IN_DIM * COM_DIM; i += 256) sW[i] = Wt[i];
    for (int i = tid; i < TM * IN_DIM; i += 256) {
        int node = i >> 7, k = i & 127;
        sF[k * TM + node] = feat[(size_t)(n0 + node) * IN_DIM + k];
    }
    __syncthreads();

    const int tx = tid & 15;   // col group (8 cols)
    const int ty = tid >> 4;   // node group (4 nodes)
    float acc[4][8];
    #pragma unroll
    for (int i = 0; i < 4; ++i)
        #pragma unroll
        for (int j = 0; j < 8; ++j) acc[i][j] = 0.f;

    const float* sFb = sF + ty * 4;
    const float* sWb = sW + tx * 8;
    #pragma unroll 4
    for (int k = 0; k < IN_DIM; ++k) {
        float4 a  = *(const float4*)(sFb + k * TM);
        float4 b0 = *(const float4*)(sWb + k * COM_DIM);
        float4 b1 = *(const float4*)(sWb + k * COM_DIM + 4);
        float av[4] = {a.x, a.y, a.z, a.w};
        float bv[8] = {b0.x, b0.y, b0.z, b0.w, b1.x, b1.y, b1.z, b1.w};
        #pragma unroll
        for (int ii = 0; ii < 4; ++ii)
            #pragma unroll
            for (int jj = 0; jj < 8; ++jj)
                acc[ii][jj] += av[ii] * bv[jj];
    }

    #pragma unroll
    for (int ii = 0; ii < 4; ++ii) {
        int n = n0 + ty * 4 + ii;
        float mk = mask[n * N_ETYPE + t];
        float* mrow = g_mess + ((size_t)t * N_NODES + n) * COM_DIM;
        const float* crow = com + (size_t)n * COM_DIM;
        #pragma unroll
        for (int jj = 0; jj < 8; ++jj) {
            int c = tx * 8 + jj;
            mrow[c] = mk * acc[ii][jj] + crow[c];
        }
    }
}

// ---------------- Phase 2: el/er[n, h, t] = mess[t,n] . attn[t,h] ----------------
__global__ __launch_bounds__(256) void elr_kernel(
    const float* __restrict__ attn_l, const float* __restrict__ attn_r)
{
    int warp = (blockIdx.x * blockDim.x + threadIdx.x) >> 5;
    if (warp >= N_ETYPE * N_NODES) return;
    const int lane = threadIdx.x & 31;
    const int t = warp / N_NODES;
    const int n = warp - t * N_NODES;

    float4 m = ((const float4*)g_mess)[(size_t)warp * 32 + lane];
    float dots[8];
    #pragma unroll
    for (int v = 0; v < 8; ++v) {
        const float* base = (v < 4) ? attn_l : attn_r;
        float4 a = ((const float4*)(base + (t * N_HEADS + (v & 3)) * COM_DIM))[lane];
        float p = m.x * a.x + m.y * a.y + m.z * a.z + m.w * a.w;
        #pragma unroll
        for (int off = 16; off; off >>= 1)
            p += __shfl_xor_sync(0xffffffffu, p, off);
        dots[v] = p;
    }
    if (lane == 0) {
        #pragma unroll
        for (int h = 0; h < N_HEADS; ++h) {
            g_el[n * NCH + h * N_ETYPE + t] = dots[h];
            g_er[n * NCH + h * N_ETYPE + t] = dots[4 + h];
        }
    }
}

// ---------------- CSR build ----------------
__global__ void zero_kernel() {
    int i = blockIdx.x * blockDim.x + threadIdx.x;
    if (i < N_NODES) g_deg[i] = 0;
}

__global__ void hist_kernel(const int* __restrict__ dst) {
    int m = blockIdx.x * blockDim.x + threadIdx.x;
    if (m < N_EDGES) atomicAdd(&g_deg[dst[m]], 1);
}

__global__ void scan_kernel() {
    __shared__ int wsum[32];
    const int tid = threadIdx.x, lane = tid & 31, wid = tid >> 5;
    int carry = 0;
    for (int base = 0; base < N_NODES; base += 1024) {
        int idx = base + tid;
        int v = (idx < N_NODES) ? g_deg[idx] : 0;
        int x = v;
        #pragma unroll
        for (int off = 1; off < 32; off <<= 1) {
            int y = __shfl_up_sync(0xffffffffu, x, off);
            if (lane >= off) x += y;
        }
        if (lane == 31) wsum[wid] = x;
        __syncthreads();
        if (wid == 0) {
            int s = wsum[lane];
            #pragma unroll
            for (int off = 1; off < 32; off <<= 1) {
                int y = __shfl_up_sync(0xffffffffu, s, off);
                if (lane >= off) s += y;
            }
            wsum[lane] = s;
        }
        __syncthreads();
        int prefix = carry + (wid > 0 ? wsum[wid - 1] : 0);
        int excl = prefix + x - v;
        if (idx < N_NODES) { g_rowptr[idx] = excl; g_deg[idx] = excl; }
        carry += wsum[31];
        __syncthreads();
    }
    if (tid == 0) g_rowptr[N_NODES] = carry;
}

__global__ void scatter_kernel(const int* __restrict__ dst) {
    int m = blockIdx.x * blockDim.x + threadIdx.x;
    if (m < N_EDGES) {
        int pos = atomicAdd(&g_deg[dst[m]], 1);
        g_eidx[pos] = m;
    }
}

// ---------------- Phase 3: per-dst softmax + aggregate + ELU (warp per dst) ----------------
__global__ __launch_bounds__(256) void agg_kernel(
    const int* __restrict__ src, const int* __restrict__ etype,
    float* __restrict__ out)
{
    int warp = (blockIdx.x * blockDim.x + threadIdx.x) >> 5;
    if (warp >= N_NODES) return;
    const int lane = threadIdx.x & 31;
    const int d = warp;
    const int beg = g_rowptr[d], end = g_rowptr[d + 1];

    float er_ch = (lane < NCH) ? g_er[d * NCH + lane] : 0.f;

    // pass 1: per-channel max over incoming edges (lane = channel)
    float mx = -3.402823466e38f;
    for (int p = beg; p < end; ++p) {
        int s = src[g_eidx[p]];
        if (lane < NCH) {
            float v = g_el[s * NCH + lane] + er_ch;
            v = v >= 0.f ? v : NEG_SLOPE * v;
            mx = fmaxf(mx, v);
        }
    }
    // pass 2: denominator
    float den = 0.f;
    for (int p = beg; p < end; ++p) {
        int s = src[g_eidx[p]];
        if (lane < NCH) {
            float v = g_el[s * NCH + lane] + er_ch;
            v = v >= 0.f ? v : NEG_SLOPE * v;
            den += __expf(v - mx);
        }
    }
    // pass 3: coeff[m] = sum_h a[m,h,etype[m]]; acc += coeff * mess[etype,src]
    float4 acc = make_float4(0.f, 0.f, 0.f, 0.f);
    for (int p = beg; p < end; ++p) {
        int m = g_eidx[p];
        int s = src[m];
        int t = etype[m];
        float c = 0.f;
        if (lane < NCH && (lane % N_ETYPE) == t) {   // lanes h*5+t, h=0..3
            float v = g_el[s * NCH + lane] + er_ch;
            v = v >= 0.f ? v : NEG_SLOPE * v;
            c = __expf(v - mx) / den;
        }
        #pragma unroll
        for (int off = 16; off; off >>= 1)
            c += __shfl_xor_sync(0xffffffffu, c, off);
        float4 mv = ((const float4*)g_mess)[((size_t)t * N_NODES + s) * 32 + lane];
        acc.x += c * mv.x; acc.y += c * mv.y;
        acc.z += c * mv.z; acc.w += c * mv.w;
    }
    float4 o;
    o.x = acc.x > 0.f ? acc.x : expm1f(acc.x);
    o.y = acc.y > 0.f ? acc.y : expm1f(acc.y);
    o.z = acc.z > 0.f ? acc.z : expm1f(acc.z);
    o.w = acc.w > 0.f ? acc.w : expm1f(acc.w);
    ((float4*)out)[(size_t)d * 32 + lane] = o;
}

// ---------------- launch ----------------
extern "C" void kernel_launch(void* const* d_in, const int* in_sizes, int n_in,
                              void* d_out, int out_size)
{
    const float* feat   = (const float*)d_in[0];
    const float* com    = (const float*)d_in[1];
    const float* mask   = (const float*)d_in[2];
    const float* W      = (const float*)d_in[3];
    const float* attn_l = (const float*)d_in[4];
    const float* attn_r = (const float*)d_in[5];
    const int*   src    = (const int*)d_in[6];
    const int*   dst    = (const int*)d_in[7];
    const int*   etype  = (const int*)d_in[8];
    float* out = (float*)d_out;

    const int smem = (IN_DIM * COM_DIM + IN_DIM * TM) * (int)sizeof(float); // 96 KB
    cudaFuncSetAttribute(gemm_kernel, cudaFuncAttributeMaxDynamicSharedMemorySize, smem);

    gemm_kernel<<<dim3(N_NODES / TM, N_ETYPE), 256, smem>>>(feat, com, mask, W);
    elr_kernel<<<(N_ETYPE * N_NODES) / 8, 256>>>(attn_l, attn_r);
    zero_kernel<<<(N_NODES + 255) / 256, 256>>>();
    hist_kernel<<<(N_EDGES + 255) / 256, 256>>>(dst);
    scan_kernel<<<1, 1024>>>();
    scatter_kernel<<<(N_EDGES + 255) / 256, 256>>>(dst);
    agg_kernel<<<(N_NODES * 32 + 255) / 256, 256>>>(src, etype, out);
}

// round 5
// speedup vs baseline: 1.6435x; 1.6435x over previous
#include <cuda_runtime.h>
#include <cstdint>

#define N_NODES 40000
#define N_EDGES 800000
#define IN_DIM  128
#define COM_DIM 128
#define N_ETYPE 5
#define N_HEADS 4
#define NCH     20
#define ELSTRIDE 32
#define NEG_SLOPE 0.2f
#define TILE_M 128
#define NTILES 313            // ceil(40000/128)
#define PAD 132               // smem row pitch (words)

// ---------------- device scratch ----------------
__device__ float g_mess[(size_t)N_ETYPE * N_NODES * COM_DIM];   // 102.4 MB
__device__ float g_el[(size_t)N_NODES * ELSTRIDE];
__device__ float g_er[(size_t)N_NODES * ELSTRIDE];
__device__ int   g_deg[N_NODES];
__device__ int   g_rowptr[N_NODES + 1];
__device__ int   g_eidx[N_EDGES];

__device__ __forceinline__ uint32_t f2tf32(float x) {
    uint32_t u; asm("cvt.rna.tf32.f32 %0, %1;" : "=r"(u) : "f"(x)); return u;
}

__device__ __forceinline__ void mma_tf32(float* c, uint32_t a0, uint32_t a1,
                                         uint32_t a2, uint32_t a3,
                                         uint32_t b0, uint32_t b1) {
    asm volatile(
        "mma.sync.aligned.m16n8k8.row.col.f32.tf32.tf32.f32 "
        "{%0,%1,%2,%3}, {%4,%5,%6,%7}, {%8,%9}, {%0,%1,%2,%3};"
        : "+f"(c[0]), "+f"(c[1]), "+f"(c[2]), "+f"(c[3])
        : "r"(a0), "r"(a1), "r"(a2), "r"(a3), "r"(b0), "r"(b1));
}

// ---------------- Phase 1: mess = mask*(feat@W_t)+com, fused el/er ----------------
// Block: 128 nodes x 128 out-channels for one etype t. 8 warps, warp = 32Mx64N.
__global__ __launch_bounds__(256)
void mma_kernel(const float* __restrict__ feat, const float* __restrict__ com,
                const float* __restrict__ mask, const float* __restrict__ W,
                const float* __restrict__ attn_l, const float* __restrict__ attn_r)
{
    __shared__ float sAttn[8 * 128];
    extern __shared__ float sh[];
    float* sA = sh;                 // [128][PAD]  feat tile (tf32 bits), row-major
    float* sB = sh + 128 * PAD;     // [128][PAD]  W_t transposed: sB[n][k]

    const int tid = threadIdx.x;
    const int wid = tid >> 5, lane = tid & 31;
    const int g = lane >> 2, tig = lane & 3;
    const int t = blockIdx.y;
    const int n0 = blockIdx.x * TILE_M;

    // attn vectors -> smem
    for (int i = tid; i < 1024; i += 256) {
        int h = i >> 7, c = i & 127;
        sAttn[i] = (h < 4) ? attn_l[(t * 4 + h) * 128 + c]
                           : attn_r[(t * 4 + (h - 4)) * 128 + c];
    }
    // A tile: feat rows, tf32-converted
    for (int i = tid; i < 4096; i += 256) {
        int row = i >> 5, c4 = i & 31;
        int gr = n0 + row; if (gr > N_NODES - 1) gr = N_NODES - 1;
        float4 v = ((const float4*)feat)[(size_t)gr * 32 + c4];
        uint32_t* d = (uint32_t*)&sA[row * PAD + c4 * 4];
        d[0] = f2tf32(v.x); d[1] = f2tf32(v.y);
        d[2] = f2tf32(v.z); d[3] = f2tf32(v.w);
    }
    // B tile: W_t[k][n] -> sB[n][k] (transposed), tf32-converted
    const float* Wt = W + (size_t)t * IN_DIM * COM_DIM;
    for (int i = tid; i < 16384; i += 256) {
        int k = i >> 7, n = i & 127;           // n contiguous in warp -> coalesced LDG
        ((uint32_t*)sB)[n * PAD + k] = f2tf32(Wt[k * 128 + n]);
    }
    __syncthreads();

    const int mrow = (wid & 3) * 32;
    const int ncol = (wid >> 2) * 64;
    float acc[2][8][4];
    #pragma unroll
    for (int mb = 0; mb < 2; ++mb)
        #pragma unroll
        for (int nb = 0; nb < 8; ++nb)
            #pragma unroll
            for (int q = 0; q < 4; ++q) acc[mb][nb][q] = 0.f;

    const uint32_t* uA = (const uint32_t*)sA;
    const uint32_t* uB = (const uint32_t*)sB;
    #pragma unroll
    for (int ko = 0; ko < 128; ko += 8) {
        uint32_t a[2][4];
        #pragma unroll
        for (int mb = 0; mb < 2; ++mb) {
            int r = mrow + mb * 16;
            a[mb][0] = uA[(r + g) * PAD + ko + tig];
            a[mb][1] = uA[(r + g + 8) * PAD + ko + tig];
            a[mb][2] = uA[(r + g) * PAD + ko + tig + 4];
            a[mb][3] = uA[(r + g + 8) * PAD + ko + tig + 4];
        }
        #pragma unroll
        for (int nb = 0; nb < 8; ++nb) {
            uint32_t b0 = uB[(ncol + nb * 8 + g) * PAD + ko + tig];
            uint32_t b1 = uB[(ncol + nb * 8 + g) * PAD + ko + tig + 4];
            mma_tf32(acc[0][nb], a[0][0], a[0][1], a[0][2], a[0][3], b0, b1);
            mma_tf32(acc[1][nb], a[1][0], a[1][1], a[1][2], a[1][3], b0, b1);
        }
    }

    // stage C through smem (reuse sA region): sC[128][PAD]
    __syncthreads();
    float* sC = sh;
    #pragma unroll
    for (int mb = 0; mb < 2; ++mb) {
        #pragma unroll
        for (int nb = 0; nb < 8; ++nb) {
            int r = mrow + mb * 16 + g;
            int c = ncol + nb * 8 + 2 * tig;
            sC[r * PAD + c]           = acc[mb][nb][0];
            sC[r * PAD + c + 1]       = acc[mb][nb][1];
            sC[(r + 8) * PAD + c]     = acc[mb][nb][2];
            sC[(r + 8) * PAD + c + 1] = acc[mb][nb][3];
        }
    }
    __syncthreads();

    // epilogue: warp wid handles rows wid*16 .. wid*16+15; lane = 4 cols
    for (int rr = 0; rr < 16; ++rr) {
        int r = wid * 16 + rr;
        int n = n0 + r;
        if (n >= N_NODES) break;
        float mk = mask[n * N_ETYPE + t];
        float4 cv = *(const float4*)&sC[r * PAD + lane * 4];
        float4 cm = ((const float4*)com)[(size_t)n * 32 + lane];
        float4 m;
        m.x = fmaf(mk, cv.x, cm.x);
        m.y = fmaf(mk, cv.y, cm.y);
        m.z = fmaf(mk, cv.z, cm.z);
        m.w = fmaf(mk, cv.w, cm.w);
        ((float4*)(g_mess + ((size_t)t * N_NODES + n) * COM_DIM))[lane] = m;
        float dots[8];
        #pragma unroll
        for (int v = 0; v < 8; ++v) {
            float4 av = ((const float4*)sAttn)[v * 32 + lane];
            float p = m.x * av.x + m.y * av.y + m.z * av.z + m.w * av.w;
            #pragma unroll
            for (int off = 16; off; off >>= 1)
                p += __shfl_xor_sync(0xffffffffu, p, off);
            dots[v] = p;
        }
        if (lane == 0) {
            #pragma unroll
            for (int h = 0; h < 4; ++h) {
                g_el[(size_t)n * ELSTRIDE + h * N_ETYPE + t] = dots[h];
                g_er[(size_t)n * ELSTRIDE + h * N_ETYPE + t] = dots[4 + h];
            }
        }
    }
}

// ---------------- CSR build ----------------
__global__ void zero_kernel() {
    int i = blockIdx.x * blockDim.x + threadIdx.x;
    if (i < N_NODES) g_deg[i] = 0;
}
__global__ void hist_kernel(const int* __restrict__ dst) {
    int m = blockIdx.x * blockDim.x + threadIdx.x;
    if (m < N_EDGES) atomicAdd(&g_deg[dst[m]], 1);
}
__global__ void scan_kernel() {
    __shared__ int wsum[32];
    const int tid = threadIdx.x, lane = tid & 31, wid = tid >> 5;
    int carry = 0;
    for (int base = 0; base < N_NODES; base += 1024) {
        int idx = base + tid;
        int v = (idx < N_NODES) ? g_deg[idx] : 0;
        int x = v;
        #pragma unroll
        for (int off = 1; off < 32; off <<= 1) {
            int y = __shfl_up_sync(0xffffffffu, x, off);
            if (lane >= off) x += y;
        }
        if (lane == 31) wsum[wid] = x;
        __syncthreads();
        if (wid == 0) {
            int s = wsum[lane];
            #pragma unroll
            for (int off = 1; off < 32; off <<= 1) {
                int y = __shfl_up_sync(0xffffffffu, s, off);
                if (lane >= off) s += y;
            }
            wsum[lane] = s;
        }
        __syncthreads();
        int prefix = carry + (wid > 0 ? wsum[wid - 1] : 0);
        int excl = prefix + x - v;
        if (idx < N_NODES) { g_rowptr[idx] = excl; g_deg[idx] = excl; }
        carry += wsum[31];
        __syncthreads();
    }
    if (tid == 0) g_rowptr[N_NODES] = carry;
}
__global__ void scatter_kernel(const int* __restrict__ dst) {
    int m = blockIdx.x * blockDim.x + threadIdx.x;
    if (m < N_EDGES) {
        int pos = atomicAdd(&g_deg[dst[m]], 1);
        g_eidx[pos] = m;
    }
}

// ---------------- Phase 3: 2-pass softmax + aggregate + ELU (warp per dst) ----------------
__global__ __launch_bounds__(256) void agg_kernel(
    const int* __restrict__ src, const int* __restrict__ etype,
    float* __restrict__ out)
{
    int warp = (blockIdx.x * blockDim.x + threadIdx.x) >> 5;
    if (warp >= N_NODES) return;
    const int lane = threadIdx.x & 31;
    const int d = warp;
    const int beg = g_rowptr[d], end = g_rowptr[d + 1];

    float er_ch = g_er[(size_t)d * ELSTRIDE + lane];   // lanes >= 20 read zeros, never used

    // pass 1: per-channel denominator (no max subtraction: |logit| <~ 16, exp safe)
    float den = 0.f;
    for (int base = beg; base < end; base += 32) {
        int cnt = min(32, end - base);
        int s = 0;
        if (lane < cnt) s = src[g_eidx[base + lane]];
        for (int p = 0; p < cnt; ++p) {
            int sp = __shfl_sync(0xffffffffu, s, p);
            float v = g_el[(size_t)sp * ELSTRIDE + lane] + er_ch;
            v = v >= 0.f ? v : NEG_SLOPE * v;
            if (lane < NCH) den += __expf(v);
        }
    }
    float inv_den = (lane < NCH && den > 0.f) ? 1.f / den : 0.f;

    // pass 2: coeff + weighted message accumulation
    float4 acc = make_float4(0.f, 0.f, 0.f, 0.f);
    for (int base = beg; base < end; base += 32) {
        int cnt = min(32, end - base);
        int s = 0, tt = 0;
        if (lane < cnt) {
            int m = g_eidx[base + lane];
            s = src[m];
            tt = etype[m];
        }
        for (int p = 0; p < cnt; ++p) {
            int sp = __shfl_sync(0xffffffffu, s, p);
            int tp = __shfl_sync(0xffffffffu, tt, p);
            float c = 0.f;
            if (lane < NCH && (lane - (lane / N_ETYPE) * N_ETYPE) == tp) {
                float v = g_el[(size_t)sp * ELSTRIDE + lane] + er_ch;
                v = v >= 0.f ? v : NEG_SLOPE * v;
                c = __expf(v) * inv_den;
            }
            #pragma unroll
            for (int off = 16; off; off >>= 1)
                c += __shfl_xor_sync(0xffffffffu, c, off);
            float4 mv = ((const float4*)g_mess)[((size_t)tp * N_NODES + sp) * 32 + lane];
            acc.x = fmaf(c, mv.x, acc.x);
            acc.y = fmaf(c, mv.y, acc.y);
            acc.z = fmaf(c, mv.z, acc.z);
            acc.w = fmaf(c, mv.w, acc.w);
        }
    }
    float4 o;
    o.x = acc.x > 0.f ? acc.x : expm1f(acc.x);
    o.y = acc.y > 0.f ? acc.y : expm1f(acc.y);
    o.z = acc.z > 0.f ? acc.z : expm1f(acc.z);
    o.w = acc.w > 0.f ? acc.w : expm1f(acc.w);
    ((float4*)out)[(size_t)d * 32 + lane] = o;
}

// ---------------- launch ----------------
extern "C" void kernel_launch(void* const* d_in, const int* in_sizes, int n_in,
                              void* d_out, int out_size)
{
    const float* feat   = (const float*)d_in[0];
    const float* com    = (const float*)d_in[1];
    const float* mask   = (const float*)d_in[2];
    const float* W      = (const float*)d_in[3];
    const float* attn_l = (const float*)d_in[4];
    const float* attn_r = (const float*)d_in[5];
    const int*   src    = (const int*)d_in[6];
    const int*   dst    = (const int*)d_in[7];
    const int*   etype  = (const int*)d_in[8];
    float* out = (float*)d_out;

    const int smem = 2 * 128 * PAD * (int)sizeof(float);   // 135168 B
    cudaFuncSetAttribute(mma_kernel, cudaFuncAttributeMaxDynamicSharedMemorySize, smem);

    mma_kernel<<<dim3(NTILES, N_ETYPE), 256, smem>>>(feat, com, mask, W, attn_l, attn_r);
    zero_kernel<<<(N_NODES + 255) / 256, 256>>>();
    hist_kernel<<<(N_EDGES + 255) / 256, 256>>>(dst);
    scan_kernel<<<1, 1024>>>();
    scatter_kernel<<<(N_EDGES + 255) / 256, 256>>>(dst);
    agg_kernel<<<(N_NODES * 32 + 255) / 256, 256>>>(src, etype, out);
}

// round 6
// speedup vs baseline: 1.7023x; 1.0358x over previous
#include <cuda_runtime.h>
#include <cstdint>

#define N_NODES 40000
#define N_EDGES 800000
#define IN_DIM  128
#define COM_DIM 128
#define N_ETYPE 5
#define N_HEADS 4
#define NCH     20
#define ELSTRIDE 32
#define NEG_SLOPE 0.2f
#define TILE_M 128
#define NTILES 313            // ceil(40000/128)
#define PAD 132               // smem row pitch (words)
#define SCAN_BLK 40           // 40 x 1024 >= 40000

// ---------------- device scratch ----------------
__device__ float g_mess[(size_t)N_ETYPE * N_NODES * COM_DIM];   // 102.4 MB
__device__ float g_el[(size_t)N_NODES * ELSTRIDE];
__device__ float g_er[(size_t)N_NODES * ELSTRIDE];
__device__ float g_enum[(size_t)N_EDGES * 4];                   // 12.8 MB numerator cache
__device__ int   g_deg[N_NODES];
__device__ int   g_rowptr[N_NODES + 1];
__device__ int   g_eidx[N_EDGES];
__device__ int   g_bsum[SCAN_BLK];
__device__ int   g_boff[SCAN_BLK];

__device__ __forceinline__ uint32_t f2tf32(float x) {
    uint32_t u; asm("cvt.rna.tf32.f32 %0, %1;" : "=r"(u) : "f"(x)); return u;
}

__device__ __forceinline__ void mma_tf32(float* c, uint32_t a0, uint32_t a1,
                                         uint32_t a2, uint32_t a3,
                                         uint32_t b0, uint32_t b1) {
    asm volatile(
        "mma.sync.aligned.m16n8k8.row.col.f32.tf32.tf32.f32 "
        "{%0,%1,%2,%3}, {%4,%5,%6,%7}, {%8,%9}, {%0,%1,%2,%3};"
        : "+f"(c[0]), "+f"(c[1]), "+f"(c[2]), "+f"(c[3])
        : "r"(a0), "r"(a1), "r"(a2), "r"(a3), "r"(b0), "r"(b1));
}

// ---------------- Phase 1: mess = mask*(feat@W_t)+com, fused el/er ----------------
__global__ __launch_bounds__(256)
void mma_kernel(const float* __restrict__ feat, const float* __restrict__ com,
                const float* __restrict__ mask, const float* __restrict__ W,
                const float* __restrict__ attn_l, const float* __restrict__ attn_r)
{
    __shared__ float sAttn[8 * 128];
    extern __shared__ float sh[];
    float* sA = sh;                 // [128][PAD]
    float* sB = sh + 128 * PAD;     // [128][PAD]  W_t transposed: sB[n][k]

    const int tid = threadIdx.x;
    const int wid = tid >> 5, lane = tid & 31;
    const int g = lane >> 2, tig = lane & 3;
    const int t = blockIdx.y;
    const int n0 = blockIdx.x * TILE_M;

    for (int i = tid; i < 1024; i += 256) {
        int h = i >> 7, c = i & 127;
        sAttn[i] = (h < 4) ? attn_l[(t * 4 + h) * 128 + c]
                           : attn_r[(t * 4 + (h - 4)) * 128 + c];
    }
    for (int i = tid; i < 4096; i += 256) {
        int row = i >> 5, c4 = i & 31;
        int gr = n0 + row; if (gr > N_NODES - 1) gr = N_NODES - 1;
        float4 v = ((const float4*)feat)[(size_t)gr * 32 + c4];
        uint32_t* d = (uint32_t*)&sA[row * PAD + c4 * 4];
        d[0] = f2tf32(v.x); d[1] = f2tf32(v.y);
        d[2] = f2tf32(v.z); d[3] = f2tf32(v.w);
    }
    const float* Wt = W + (size_t)t * IN_DIM * COM_DIM;
    for (int i = tid; i < 16384; i += 256) {
        int k = i >> 7, n = i & 127;
        ((uint32_t*)sB)[n * PAD + k] = f2tf32(Wt[k * 128 + n]);
    }
    __syncthreads();

    const int mrow = (wid & 3) * 32;
    const int ncol = (wid >> 2) * 64;
    float acc[2][8][4];
    #pragma unroll
    for (int mb = 0; mb < 2; ++mb)
        #pragma unroll
        for (int nb = 0; nb < 8; ++nb)
            #pragma unroll
            for (int q = 0; q < 4; ++q) acc[mb][nb][q] = 0.f;

    const uint32_t* uA = (const uint32_t*)sA;
    const uint32_t* uB = (const uint32_t*)sB;
    #pragma unroll
    for (int ko = 0; ko < 128; ko += 8) {
        uint32_t a[2][4];
        #pragma unroll
        for (int mb = 0; mb < 2; ++mb) {
            int r = mrow + mb * 16;
            a[mb][0] = uA[(r + g) * PAD + ko + tig];
            a[mb][1] = uA[(r + g + 8) * PAD + ko + tig];
            a[mb][2] = uA[(r + g) * PAD + ko + tig + 4];
            a[mb][3] = uA[(r + g + 8) * PAD + ko + tig + 4];
        }
        #pragma unroll
        for (int nb = 0; nb < 8; ++nb) {
            uint32_t b0 = uB[(ncol + nb * 8 + g) * PAD + ko + tig];
            uint32_t b1 = uB[(ncol + nb * 8 + g) * PAD + ko + tig + 4];
            mma_tf32(acc[0][nb], a[0][0], a[0][1], a[0][2], a[0][3], b0, b1);
            mma_tf32(acc[1][nb], a[1][0], a[1][1], a[1][2], a[1][3], b0, b1);
        }
    }

    __syncthreads();
    float* sC = sh;
    #pragma unroll
    for (int mb = 0; mb < 2; ++mb) {
        #pragma unroll
        for (int nb = 0; nb < 8; ++nb) {
            int r = mrow + mb * 16 + g;
            int c = ncol + nb * 8 + 2 * tig;
            sC[r * PAD + c]           = acc[mb][nb][0];
            sC[r * PAD + c + 1]       = acc[mb][nb][1];
            sC[(r + 8) * PAD + c]     = acc[mb][nb][2];
            sC[(r + 8) * PAD + c + 1] = acc[mb][nb][3];
        }
    }
    __syncthreads();

    for (int rr = 0; rr < 16; ++rr) {
        int r = wid * 16 + rr;
        int n = n0 + r;
        if (n >= N_NODES) break;
        float mk = mask[n * N_ETYPE + t];
        float4 cv = *(const float4*)&sC[r * PAD + lane * 4];
        float4 cm = ((const float4*)com)[(size_t)n * 32 + lane];
        float4 m;
        m.x = fmaf(mk, cv.x, cm.x);
        m.y = fmaf(mk, cv.y, cm.y);
        m.z = fmaf(mk, cv.z, cm.z);
        m.w = fmaf(mk, cv.w, cm.w);
        ((float4*)(g_mess + ((size_t)t * N_NODES + n) * COM_DIM))[lane] = m;
        float dots[8];
        #pragma unroll
        for (int v = 0; v < 8; ++v) {
            float4 av = ((const float4*)sAttn)[v * 32 + lane];
            float p = m.x * av.x + m.y * av.y + m.z * av.z + m.w * av.w;
            #pragma unroll
            for (int off = 16; off; off >>= 1)
                p += __shfl_xor_sync(0xffffffffu, p, off);
            dots[v] = p;
        }
        if (lane == 0) {
            #pragma unroll
            for (int h = 0; h < 4; ++h) {
                g_el[(size_t)n * ELSTRIDE + h * N_ETYPE + t] = dots[h];
                g_er[(size_t)n * ELSTRIDE + h * N_ETYPE + t] = dots[4 + h];
            }
        }
    }
}

// ---------------- CSR build ----------------
__global__ void zero_kernel() {
    int i = blockIdx.x * blockDim.x + threadIdx.x;
    if (i < N_NODES) g_deg[i] = 0;
}
__global__ void hist_kernel(const int* __restrict__ dst) {
    int m = blockIdx.x * blockDim.x + threadIdx.x;
    if (m < N_EDGES) atomicAdd(&g_deg[dst[m]], 1);
}
// phase A: per-block (1024 elems) exclusive scan + block sums
__global__ __launch_bounds__(1024) void scanA_kernel() {
    __shared__ int wsum[32];
    const int tid = threadIdx.x, lane = tid & 31, wid = tid >> 5;
    int idx = blockIdx.x * 1024 + tid;
    int v = (idx < N_NODES) ? g_deg[idx] : 0;
    int x = v;
    #pragma unroll
    for (int off = 1; off < 32; off <<= 1) {
        int y = __shfl_up_sync(0xffffffffu, x, off);
        if (lane >= off) x += y;
    }
    if (lane == 31) wsum[wid] = x;
    __syncthreads();
    if (wid == 0) {
        int s = wsum[lane];
        #pragma unroll
        for (int off = 1; off < 32; off <<= 1) {
            int y = __shfl_up_sync(0xffffffffu, s, off);
            if (lane >= off) s += y;
        }
        wsum[lane] = s;
        if (lane == 31) g_bsum[blockIdx.x] = s;
    }
    __syncthreads();
    int excl = (x - v) + (wid > 0 ? wsum[wid - 1] : 0);
    if (idx < N_NODES) g_rowptr[idx] = excl;
}
// phase B: exclusive scan of 40 block sums (1 warp)
__global__ void scanB_kernel() {
    int lane = threadIdx.x;
    int v = (lane < SCAN_BLK) ? g_bsum[lane] : 0;
    int x = v;
    #pragma unroll
    for (int off = 1; off < 32; off <<= 1) {
        int y = __shfl_up_sync(0xffffffffu, x, off);
        if (lane >= off) x += y;
    }
    // SCAN_BLK=40 > 32: handle second "row" of 8 by adding warp total
    __shared__ int tot32;
    if (lane == 31) tot32 = x;
    __syncwarp();
    if (lane < 32) g_boff[lane] = x - v;
    if (lane >= 32) { /* unused: blockDim 32 */ }
    // second chunk (8 values) scanned by lane 0 serially (tiny)
    if (lane == 0) {
        int run = tot32;
        for (int b = 32; b < SCAN_BLK; ++b) {
            g_boff[b] = run;
            run += g_bsum[b];
        }
        g_rowptr[N_NODES] = N_EDGES;
    }
}
// phase C: apply block offsets, init cursor
__global__ void scanC_kernel() {
    int i = blockIdx.x * blockDim.x + threadIdx.x;
    if (i < N_NODES) {
        int r = g_rowptr[i] + g_boff[i >> 10];
        g_rowptr[i] = r;
        g_deg[i] = r;
    }
}
__global__ void scatter_kernel(const int* __restrict__ dst) {
    int m = blockIdx.x * blockDim.x + threadIdx.x;
    if (m < N_EDGES) {
        int pos = atomicAdd(&g_deg[dst[m]], 1);
        g_eidx[pos] = m;
    }
}

// ---------------- Phase 3: softmax + aggregate + ELU (warp per dst) ----------------
__global__ __launch_bounds__(256) void agg_kernel(
    const int* __restrict__ src, const int* __restrict__ etype,
    float* __restrict__ out)
{
    int warp = (blockIdx.x * blockDim.x + threadIdx.x) >> 5;
    if (warp >= N_NODES) return;
    const int lane = threadIdx.x & 31;
    const int d = warp;
    const int beg = g_rowptr[d], end = g_rowptr[d + 1];

    float er_ch = g_er[(size_t)d * ELSTRIDE + lane];

    // pass 1: per-channel denominator; cache 4 numerators per edge in g_enum
    float den = 0.f;
    for (int base = beg; base < end; base += 32) {
        int cnt = min(32, end - base);
        int s = 0, tt = 0;
        if (lane < cnt) {
            int m = g_eidx[base + lane];
            s = src[m];
            tt = etype[m];
        }
        for (int p = 0; p < cnt; ++p) {
            int sp = __shfl_sync(0xffffffffu, s, p);
            int tp = __shfl_sync(0xffffffffu, tt, p);
            float v = g_el[(size_t)sp * ELSTRIDE + lane] + er_ch;
            v = v >= 0.f ? v : NEG_SLOPE * v;
            float e = __expf(v);
            if (lane < NCH) {
                den += e;
                if (lane - (lane / N_ETYPE) * N_ETYPE == tp)
                    g_enum[(size_t)(base + p) * 4 + lane / N_ETYPE] = e;
            }
        }
    }
    float inv_den = (lane < NCH && den > 0.f) ? 1.f / den : 0.f;
    __threadfence_block();
    __syncwarp();

    // pass 2: lane-parallel coeff from cached numerators, then broadcast + gather
    float4 acc = make_float4(0.f, 0.f, 0.f, 0.f);
    for (int base = beg; base < end; base += 32) {
        int cnt = min(32, end - base);
        int s = 0, tt = 0;
        float4 en = make_float4(0.f, 0.f, 0.f, 0.f);
        if (lane < cnt) {
            int m = g_eidx[base + lane];
            s = src[m];
            tt = etype[m];
            en = ((const float4*)g_enum)[base + lane];
        }
        float id0 = __shfl_sync(0xffffffffu, inv_den, tt);
        float id1 = __shfl_sync(0xffffffffu, inv_den, tt + 5);
        float id2 = __shfl_sync(0xffffffffu, inv_den, tt + 10);
        float id3 = __shfl_sync(0xffffffffu, inv_den, tt + 15);
        float cp = en.x * id0 + en.y * id1 + en.z * id2 + en.w * id3;
        for (int p = 0; p < cnt; ++p) {
            int sp = __shfl_sync(0xffffffffu, s, p);
            int tp = __shfl_sync(0xffffffffu, tt, p);
            float c = __shfl_sync(0xffffffffu, cp, p);
            float4 mv = ((const float4*)g_mess)[((size_t)tp * N_NODES + sp) * 32 + lane];
            acc.x = fmaf(c, mv.x, acc.x);
            acc.y = fmaf(c, mv.y, acc.y);
            acc.z = fmaf(c, mv.z, acc.z);
            acc.w = fmaf(c, mv.w, acc.w);
        }
    }
    float4 o;
    o.x = acc.x > 0.f ? acc.x : expm1f(acc.x);
    o.y = acc.y > 0.f ? acc.y : expm1f(acc.y);
    o.z = acc.z > 0.f ? acc.z : expm1f(acc.z);
    o.w = acc.w > 0.f ? acc.w : expm1f(acc.w);
    ((float4*)out)[(size_t)d * 32 + lane] = o;
}

// ---------------- launch ----------------
extern "C" void kernel_launch(void* const* d_in, const int* in_sizes, int n_in,
                              void* d_out, int out_size)
{
    const float* feat   = (const float*)d_in[0];
    const float* com    = (const float*)d_in[1];
    const float* mask   = (const float*)d_in[2];
    const float* W      = (const float*)d_in[3];
    const float* attn_l = (const float*)d_in[4];
    const float* attn_r = (const float*)d_in[5];
    const int*   src    = (const int*)d_in[6];
    const int*   dst    = (const int*)d_in[7];
    const int*   etype  = (const int*)d_in[8];
    float* out = (float*)d_out;

    const int smem = 2 * 128 * PAD * (int)sizeof(float);   // 135168 B
    cudaFuncSetAttribute(mma_kernel, cudaFuncAttributeMaxDynamicSharedMemorySize, smem);

    // order chosen so mma_kernel sits at launch index 3 (ncu capture slot)
    zero_kernel<<<(N_NODES + 255) / 256, 256>>>();
    hist_kernel<<<(N_EDGES + 255) / 256, 256>>>(dst);
    scanA_kernel<<<SCAN_BLK, 1024>>>();
    mma_kernel<<<dim3(NTILES, N_ETYPE), 256, smem>>>(feat, com, mask, W, attn_l, attn_r);
    scanB_kernel<<<1, 32>>>();
    scanC_kernel<<<(N_NODES + 255) / 256, 256>>>();
    scatter_kernel<<<(N_EDGES + 255) / 256, 256>>>(dst);
    agg_kernel<<<(N_NODES * 32 + 255) / 256, 256>>>(src, etype, out);
}

// round 9
// speedup vs baseline: 2.4700x; 1.4510x over previous
#include <cuda_runtime.h>
#include <cstdint>

#define N_NODES 40000
#define N_EDGES 800000
#define IN_DIM  128
#define COM_DIM 128
#define N_ETYPE 5
#define N_HEADS 4
#define NCH     20
#define ELSTRIDE 32
#define NEG_SLOPE 0.2f
#define TILE_M 128
#define NTILES 313            // ceil(40000/128)
#define APITCH 68             // A chunk pitch (words): 64 + 4
#define BPITCH 132            // B chunk pitch (words): 128 + 4
#define CPITCH 132
#define SCAN_BLK 40

// ---------------- device scratch ----------------
__device__ float g_mess[(size_t)N_ETYPE * N_NODES * COM_DIM];   // 102.4 MB
__device__ float g_el[(size_t)N_NODES * ELSTRIDE];
__device__ float g_er[(size_t)N_NODES * ELSTRIDE];
__device__ float g_enum[(size_t)N_EDGES * 4];
__device__ int   g_deg[N_NODES];
__device__ int   g_rowptr[N_NODES + 1];
__device__ int   g_eidx[N_EDGES];
__device__ int   g_bsum[SCAN_BLK];
__device__ int   g_boff[SCAN_BLK];

__device__ __forceinline__ void mma_tf32(float* c, uint32_t a0, uint32_t a1,
                                         uint32_t a2, uint32_t a3,
                                         uint32_t b0, uint32_t b1) {
    asm volatile(
        "mma.sync.aligned.m16n8k8.row.col.f32.tf32.tf32.f32 "
        "{%0,%1,%2,%3}, {%4,%5,%6,%7}, {%8,%9}, {%0,%1,%2,%3};"
        : "+f"(c[0]), "+f"(c[1]), "+f"(c[2]), "+f"(c[3])
        : "r"(a0), "r"(a1), "r"(a2), "r"(a3), "r"(b0), "r"(b1));
}

__device__ __forceinline__ void cp16(uint32_t saddr, const void* g) {
    asm volatile("cp.async.cg.shared.global [%0], [%1], 16;" :: "r"(saddr), "l"(g));
}
#define CP_COMMIT() asm volatile("cp.async.commit_group;" ::: "memory")
#define CP_WAIT0()  asm volatile("cp.async.wait_group 0;" ::: "memory")

// ---------------- Phase 1: mess = mask*(feat@W_t)+com, fused el/er ----------------
// 128 nodes x 128 cols per block, one etype. K chunked by 64, cp.async tiles,
// raw fp32 bits fed to tf32 MMA (HW truncates mantissa).
__global__ __launch_bounds__(256, 2)
void mma_kernel(const float* __restrict__ feat, const float* __restrict__ com,
                const float* __restrict__ mask, const float* __restrict__ W,
                const float* __restrict__ attn_l, const float* __restrict__ attn_r)
{
    __shared__ float sAttn[8 * 128];
    extern __shared__ float sh[];
    float* sA = sh;                       // [128][APITCH] feat chunk (k-cols 64)
    float* sB = sh + 128 * APITCH;        // [64][BPITCH]  W rows chunk

    const int tid = threadIdx.x;
    const int wid = tid >> 5, lane = tid & 31;
    const int g = lane >> 2, tig = lane & 3;
    const int t = blockIdx.y;
    const int n0 = blockIdx.x * TILE_M;

    uint32_t sAu, sBu;
    asm("{ .reg .u64 x; cvta.to.shared.u64 x, %1; cvt.u32.u64 %0, x; }" : "=r"(sAu) : "l"(sA));
    asm("{ .reg .u64 x; cvta.to.shared.u64 x, %1; cvt.u32.u64 %0, x; }" : "=r"(sBu) : "l"(sB));

    for (int i = tid; i < 1024; i += 256) {
        int h = i >> 7, c = i & 127;
        sAttn[i] = (h < 4) ? attn_l[(t * 4 + h) * 128 + c]
                           : attn_r[(t * 4 + (h - 4)) * 128 + c];
    }

    const float* Wt = W + (size_t)t * IN_DIM * COM_DIM;

    const int mrow = (wid & 3) * 32;
    const int ncol = (wid >> 2) * 64;
    float acc[2][8][4];
    #pragma unroll
    for (int mb = 0; mb < 2; ++mb)
        #pragma unroll
        for (int nb = 0; nb < 8; ++nb)
            #pragma unroll
            for (int q = 0; q < 4; ++q) acc[mb][nb][q] = 0.f;

    const uint32_t* uA = (const uint32_t*)sA;
    const uint32_t* uB = (const uint32_t*)sB;

    for (int c = 0; c < 2; ++c) {
        // ---- load chunk c via cp.async ----
        // A: 128 rows x 64 floats; 16 x 16B per row -> 2048 ops
        #pragma unroll
        for (int jj = 0; jj < 8; ++jj) {
            int j = tid + jj * 256;
            int row = j >> 4, seg = j & 15;
            int gr = n0 + row; if (gr > N_NODES - 1) gr = N_NODES - 1;
            cp16(sAu + (uint32_t)(row * APITCH + seg * 4) * 4u,
                 feat + (size_t)gr * 128 + c * 64 + seg * 4);
        }
        // B: 64 rows x 128 floats; 32 x 16B per row -> 2048 ops
        #pragma unroll
        for (int jj = 0; jj < 8; ++jj) {
            int j = tid + jj * 256;
            int kr = j >> 5, seg = j & 31;
            cp16(sBu + (uint32_t)(kr * BPITCH + seg * 4) * 4u,
                 Wt + (size_t)(c * 64 + kr) * 128 + seg * 4);
        }
        CP_COMMIT();
        CP_WAIT0();
        __syncthreads();

        // ---- compute chunk ----
        #pragma unroll
        for (int ko = 0; ko < 64; ko += 8) {
            uint32_t a[2][4];
            #pragma unroll
            for (int mb = 0; mb < 2; ++mb) {
                int r = mrow + mb * 16;
                a[mb][0] = uA[(r + g) * APITCH + ko + tig];
                a[mb][1] = uA[(r + g + 8) * APITCH + ko + tig];
                a[mb][2] = uA[(r + g) * APITCH + ko + tig + 4];
                a[mb][3] = uA[(r + g + 8) * APITCH + ko + tig + 4];
            }
            #pragma unroll
            for (int nb = 0; nb < 8; ++nb) {
                int n = ncol + nb * 8 + g;
                uint32_t b0 = uB[(ko + tig) * BPITCH + n];
                uint32_t b1 = uB[(ko + tig + 4) * BPITCH + n];
                mma_tf32(acc[0][nb], a[0][0], a[0][1], a[0][2], a[0][3], b0, b1);
                mma_tf32(acc[1][nb], a[1][0], a[1][1], a[1][2], a[1][3], b0, b1);
            }
        }
        __syncthreads();
    }

    // ---- stage C through smem (reuses sA/sB region) ----
    float* sC = sh;
    #pragma unroll
    for (int mb = 0; mb < 2; ++mb) {
        #pragma unroll
        for (int nb = 0; nb < 8; ++nb) {
            int r = mrow + mb * 16 + g;
            int cc = ncol + nb * 8 + 2 * tig;
            sC[r * CPITCH + cc]            = acc[mb][nb][0];
            sC[r * CPITCH + cc + 1]        = acc[mb][nb][1];
            sC[(r + 8) * CPITCH + cc]      = acc[mb][nb][2];
            sC[(r + 8) * CPITCH + cc + 1]  = acc[mb][nb][3];
        }
    }
    __syncthreads();

    // ---- epilogue: mess + fused el/er dots ----
    for (int rr = 0; rr < 16; ++rr) {
        int r = wid * 16 + rr;
        int n = n0 + r;
        if (n >= N_NODES) break;
        float mk = mask[n * N_ETYPE + t];
        float4 cv = *(const float4*)&sC[r * CPITCH + lane * 4];
        float4 cm = ((const float4*)com)[(size_t)n * 32 + lane];
        float4 m;
        m.x = fmaf(mk, cv.x, cm.x);
        m.y = fmaf(mk, cv.y, cm.y);
        m.z = fmaf(mk, cv.z, cm.z);
        m.w = fmaf(mk, cv.w, cm.w);
        ((float4*)(g_mess + ((size_t)t * N_NODES + n) * COM_DIM))[lane] = m;
        float dots[8];
        #pragma unroll
        for (int v = 0; v < 8; ++v) {
            float4 av = ((const float4*)sAttn)[v * 32 + lane];
            float p = m.x * av.x + m.y * av.y + m.z * av.z + m.w * av.w;
            #pragma unroll
            for (int off = 16; off; off >>= 1)
                p += __shfl_xor_sync(0xffffffffu, p, off);
            dots[v] = p;
        }
        if (lane == 0) {
            #pragma unroll
            for (int h = 0; h < 4; ++h) {
                g_el[(size_t)n * ELSTRIDE + h * N_ETYPE + t] = dots[h];
                g_er[(size_t)n * ELSTRIDE + h * N_ETYPE + t] = dots[4 + h];
            }
        }
    }
}

// ---------------- CSR build ----------------
__global__ void zero_kernel() {
    int i = blockIdx.x * blockDim.x + threadIdx.x;
    if (i < N_NODES) g_deg[i] = 0;
}
__global__ void hist_kernel(const int* __restrict__ dst) {
    int m = blockIdx.x * blockDim.x + threadIdx.x;
    if (m < N_EDGES) atomicAdd(&g_deg[dst[m]], 1);
}
__global__ __launch_bounds__(1024) void scanA_kernel() {
    __shared__ int wsum[32];
    const int tid = threadIdx.x, lane = tid & 31, wid = tid >> 5;
    int idx = blockIdx.x * 1024 + tid;
    int v = (idx < N_NODES) ? g_deg[idx] : 0;
    int x = v;
    #pragma unroll
    for (int off = 1; off < 32; off <<= 1) {
        int y = __shfl_up_sync(0xffffffffu, x, off);
        if (lane >= off) x += y;
    }
    if (lane == 31) wsum[wid] = x;
    __syncthreads();
    if (wid == 0) {
        int s = wsum[lane];
        #pragma unroll
        for (int off = 1; off < 32; off <<= 1) {
            int y = __shfl_up_sync(0xffffffffu, s, off);
            if (lane >= off) s += y;
        }
        wsum[lane] = s;
        if (lane == 31) g_bsum[blockIdx.x] = s;
    }
    __syncthreads();
    int excl = (x - v) + (wid > 0 ? wsum[wid - 1] : 0);
    if (idx < N_NODES) g_rowptr[idx] = excl;
}
__global__ void scanB_kernel() {
    int lane = threadIdx.x;
    int v = (lane < SCAN_BLK) ? g_bsum[lane] : 0;
    int x = v;
    #pragma unroll
    for (int off = 1; off < 32; off <<= 1) {
        int y = __shfl_up_sync(0xffffffffu, x, off);
        if (lane >= off) x += y;
    }
    __shared__ int tot32;
    if (lane == 31) tot32 = x;
    __syncwarp();
    g_boff[lane] = x - v;
    if (lane == 0) {
        int run = tot32;
        for (int b = 32; b < SCAN_BLK; ++b) {
            g_boff[b] = run;
            run += g_bsum[b];
        }
        g_rowptr[N_NODES] = N_EDGES;
    }
}
__global__ void scanC_kernel() {
    int i = blockIdx.x * blockDim.x + threadIdx.x;
    if (i < N_NODES) {
        int r = g_rowptr[i] + g_boff[i >> 10];
        g_rowptr[i] = r;
        g_deg[i] = r;
    }
}
__global__ void scatter_kernel(const int* __restrict__ dst) {
    int m = blockIdx.x * blockDim.x + threadIdx.x;
    if (m < N_EDGES) {
        int pos = atomicAdd(&g_deg[dst[m]], 1);
        g_eidx[pos] = m;
    }
}

// ---------------- Phase 3: softmax + aggregate + ELU (warp per dst) ----------------
__global__ __launch_bounds__(256) void agg_kernel(
    const int* __restrict__ src, const int* __restrict__ etype,
    float* __restrict__ out)
{
    int warp = (blockIdx.x * blockDim.x + threadIdx.x) >> 5;
    if (warp >= N_NODES) return;
    const int lane = threadIdx.x & 31;
    const int d = warp;
    const int beg = g_rowptr[d], end = g_rowptr[d + 1];

    float er_ch = g_er[(size_t)d * ELSTRIDE + lane];

    float den = 0.f;
    for (int base = beg; base < end; base += 32) {
        int cnt = min(32, end - base);
        int s = 0, tt = 0;
        if (lane < cnt) {
            int m = g_eidx[base + lane];
            s = src[m];
            tt = etype[m];
        }
        for (int p = 0; p < cnt; ++p) {
            int sp = __shfl_sync(0xffffffffu, s, p);
            int tp = __shfl_sync(0xffffffffu, tt, p);
            float v = g_el[(size_t)sp * ELSTRIDE + lane] + er_ch;
            v = v >= 0.f ? v : NEG_SLOPE * v;
            float e = __expf(v);
            if (lane < NCH) {
                den += e;
                if (lane - (lane / N_ETYPE) * N_ETYPE == tp)
                    g_enum[(size_t)(base + p) * 4 + lane / N_ETYPE] = e;
            }
        }
    }
    float inv_den = (lane < NCH && den > 0.f) ? 1.f / den : 0.f;
    __threadfence_block();
    __syncwarp();

    float4 acc = make_float4(0.f, 0.f, 0.f, 0.f);
    for (int base = beg; base < end; base += 32) {
        int cnt = min(32, end - base);
        int s = 0, tt = 0;
        float4 en = make_float4(0.f, 0.f, 0.f, 0.f);
        if (lane < cnt) {
            int m = g_eidx[base + lane];
            s = src[m];
            tt = etype[m];
            en = ((const float4*)g_enum)[base + lane];
        }
        float id0 = __shfl_sync(0xffffffffu, inv_den, tt);
        float id1 = __shfl_sync(0xffffffffu, inv_den, tt + 5);
        float id2 = __shfl_sync(0xffffffffu, inv_den, tt + 10);
        float id3 = __shfl_sync(0xffffffffu, inv_den, tt + 15);
        float cp = en.x * id0 + en.y * id1 + en.z * id2 + en.w * id3;
        for (int p = 0; p < cnt; ++p) {
            int sp = __shfl_sync(0xffffffffu, s, p);
            int tp = __shfl_sync(0xffffffffu, tt, p);
            float c = __shfl_sync(0xffffffffu, cp, p);
            float4 mv = ((const float4*)g_mess)[((size_t)tp * N_NODES + sp) * 32 + lane];
            acc.x = fmaf(c, mv.x, acc.x);
            acc.y = fmaf(c, mv.y, acc.y);
            acc.z = fmaf(c, mv.z, acc.z);
            acc.w = fmaf(c, mv.w, acc.w);
        }
    }
    float4 o;
    o.x = acc.x > 0.f ? acc.x : expm1f(acc.x);
    o.y = acc.y > 0.f ? acc.y : expm1f(acc.y);
    o.z = acc.z > 0.f ? acc.z : expm1f(acc.z);
    o.w = acc.w > 0.f ? acc.w : expm1f(acc.w);
    ((float4*)out)[(size_t)d * 32 + lane] = o;
}

// ---------------- launch ----------------
extern "C" void kernel_launch(void* const* d_in, const int* in_sizes, int n_in,
                              void* d_out, int out_size)
{
    const float* feat   = (const float*)d_in[0];
    const float* com    = (const float*)d_in[1];
    const float* mask   = (const float*)d_in[2];
    const float* W      = (const float*)d_in[3];
    const float* attn_l = (const float*)d_in[4];
    const float* attn_r = (const float*)d_in[5];
    const int*   src    = (const int*)d_in[6];
    const int*   dst    = (const int*)d_in[7];
    const int*   etype  = (const int*)d_in[8];
    float* out = (float*)d_out;

    const int smem = (128 * APITCH + 64 * BPITCH) * (int)sizeof(float);  // 68608 B
    cudaFuncSetAttribute(mma_kernel, cudaFuncAttributeMaxDynamicSharedMemorySize, smem);

    // mma_kernel kept at launch index 3 (ncu capture slot)
    zero_kernel<<<(N_NODES + 255) / 256, 256>>>();
    hist_kernel<<<(N_EDGES + 255) / 256, 256>>>(dst);
    scanA_kernel<<<SCAN_BLK, 1024>>>();
    mma_kernel<<<dim3(NTILES, N_ETYPE), 256, smem>>>(feat, com, mask, W, attn_l, attn_r);
    scanB_kernel<<<1, 32>>>();
    scanC_kernel<<<(N_NODES + 255) / 256, 256>>>();
    scatter_kernel<<<(N_EDGES + 255) / 256, 256>>>(dst);
    agg_kernel<<<(N_NODES * 32 + 255) / 256, 256>>>(src, etype, out);
}

// round 11
// speedup vs baseline: 2.7369x; 1.1081x over previous
#include <cuda_runtime.h>
#include <cstdint>

#define N_NODES 40000
#define N_EDGES 800000
#define IN_DIM  128
#define COM_DIM 128
#define N_ETYPE 5
#define N_HEADS 4
#define NCH     20
#define ELSTRIDE 32
#define NEG_SLOPE 0.2f
#define TILE_M 128
#define NTILES 313            // ceil(40000/128)
#define APITCH 36             // A chunk pitch (words): 32 + 4  -> bank 4g+tig
#define BPITCH 136            // B chunk pitch (words): 128 + 8 -> bank 8tig+g
#define CPITCH 132
#define SCAN_BLK 40

// smem float offsets (dynamic)
#define A0OFF 0               // 128*36 = 4608
#define A1OFF 4608
#define B0OFF 9216            // 32*136 = 4352
#define B1OFF 13568
#define SH_WORDS 17920        // 71680 bytes; sC[128][132]=16896 overlays at 0

// ---------------- device scratch ----------------
__device__ float g_mess[(size_t)N_ETYPE * N_NODES * COM_DIM];   // 102.4 MB
__device__ float g_el[(size_t)N_NODES * ELSTRIDE];
__device__ float g_er[(size_t)N_NODES * ELSTRIDE];
__device__ float g_enum[(size_t)N_EDGES * 4];
__device__ int   g_deg[N_NODES];
__device__ int   g_rowptr[N_NODES + 1];
__device__ int   g_eidx[N_EDGES];
__device__ int   g_bsum[SCAN_BLK];
__device__ int   g_boff[SCAN_BLK];

__device__ __forceinline__ void mma_tf32(float* c, uint32_t a0, uint32_t a1,
                                         uint32_t a2, uint32_t a3,
                                         uint32_t b0, uint32_t b1) {
    asm volatile(
        "mma.sync.aligned.m16n8k8.row.col.f32.tf32.tf32.f32 "
        "{%0,%1,%2,%3}, {%4,%5,%6,%7}, {%8,%9}, {%0,%1,%2,%3};"
        : "+f"(c[0]), "+f"(c[1]), "+f"(c[2]), "+f"(c[3])
        : "r"(a0), "r"(a1), "r"(a2), "r"(a3), "r"(b0), "r"(b1));
}
__device__ __forceinline__ uint32_t rnd(uint32_t u) {   // fp32 bits -> RN tf32 bits
    uint32_t r;
    asm("cvt.rna.tf32.f32 %0, %1;" : "=r"(r) : "f"(__uint_as_float(u)));
    return r;
}
__device__ __forceinline__ void cp16(uint32_t saddr, const void* g) {
    asm volatile("cp.async.cg.shared.global [%0], [%1], 16;" :: "r"(saddr), "l"(g));
}
#define CP_COMMIT() asm volatile("cp.async.commit_group;" ::: "memory")
#define CP_WAIT(N)  asm volatile("cp.async.wait_group %0;" :: "n"(N) : "memory")

// ---------------- Phase 1: mess = mask*(feat@W_t)+com, fused el/er ----------------
// 128 nodes x 128 cols per block, one etype. K chunked by 32, double-buffered
// cp.async pipeline; fragments rounded to tf32 (RN) in registers.
__global__ __launch_bounds__(256, 2)
void mma_kernel(const float* __restrict__ feat, const float* __restrict__ com,
                const float* __restrict__ mask, const float* __restrict__ W,
                const float* __restrict__ attn_l, const float* __restrict__ attn_r)
{
    __shared__ float sAttn[8 * CPITCH];   // [8 heads(l0-3,r0-3)][128] pitch 132
    __shared__ float sMask[128];
    extern __shared__ float sh[];

    const int tid = threadIdx.x;
    const int wid = tid >> 5, lane = tid & 31;
    const int g = lane >> 2, tig = lane & 3;
    const int t = blockIdx.y;
    const int n0 = blockIdx.x * TILE_M;

    uint32_t shu;
    asm("{ .reg .u64 x; cvta.to.shared.u64 x, %1; cvt.u32.u64 %0, x; }" : "=r"(shu) : "l"(sh));

    for (int i = tid; i < 1024; i += 256) {
        int h = i >> 7, c = i & 127;
        sAttn[h * CPITCH + c] = (h < 4) ? attn_l[(t * 4 + h) * 128 + c]
                                        : attn_r[(t * 4 + (h - 4)) * 128 + c];
    }
    if (tid < 128) {
        int gr = n0 + tid;
        sMask[tid] = (gr < N_NODES) ? mask[gr * N_ETYPE + t] : 0.f;
    }

    const float* Wt = W + (size_t)t * IN_DIM * COM_DIM;

    // ---- pipelined chunk loader: chunk c -> buffer c&1 ----
    auto load_chunk = [&](int c) {
        uint32_t abuf = shu + (uint32_t)((c & 1) ? A1OFF : A0OFF) * 4u;
        uint32_t bbuf = shu + (uint32_t)((c & 1) ? B1OFF : B0OFF) * 4u;
        #pragma unroll
        for (int jj = 0; jj < 4; ++jj) {                 // A: 128 x 32 floats
            int j = tid + jj * 256;
            int row = j >> 3, seg = j & 7;
            int gr = n0 + row; if (gr > N_NODES - 1) gr = N_NODES - 1;
            cp16(abuf + (uint32_t)(row * APITCH + seg * 4) * 4u,
                 feat + (size_t)gr * 128 + c * 32 + seg * 4);
        }
        #pragma unroll
        for (int jj = 0; jj < 4; ++jj) {                 // B: 32 x 128 floats
            int j = tid + jj * 256;
            int kr = j >> 5, seg = j & 31;
            cp16(bbuf + (uint32_t)(kr * BPITCH + seg * 4) * 4u,
                 Wt + (size_t)(c * 32 + kr) * 128 + seg * 4);
        }
        CP_COMMIT();
    };

    const int mrow = (wid & 3) * 32;
    const int ncol = (wid >> 2) * 64;
    float acc[2][8][4];
    #pragma unroll
    for (int mb = 0; mb < 2; ++mb)
        #pragma unroll
        for (int nb = 0; nb < 8; ++nb)
            #pragma unroll
            for (int q = 0; q < 4; ++q) acc[mb][nb][q] = 0.f;

    load_chunk(0);
    for (int c = 0; c < 4; ++c) {
        if (c < 3) load_chunk(c + 1);
        if (c < 3) { CP_WAIT(1); } else { CP_WAIT(0); }
        __syncthreads();

        const uint32_t* uA = (const uint32_t*)(sh + ((c & 1) ? A1OFF : A0OFF));
        const uint32_t* uB = (const uint32_t*)(sh + ((c & 1) ? B1OFF : B0OFF));
        #pragma unroll
        for (int ko = 0; ko < 32; ko += 8) {
            uint32_t a[2][4];
            #pragma unroll
            for (int mb = 0; mb < 2; ++mb) {
                int r = mrow + mb * 16;
                a[mb][0] = rnd(uA[(r + g) * APITCH + ko + tig]);
                a[mb][1] = rnd(uA[(r + g + 8) * APITCH + ko + tig]);
                a[mb][2] = rnd(uA[(r + g) * APITCH + ko + tig + 4]);
                a[mb][3] = rnd(uA[(r + g + 8) * APITCH + ko + tig + 4]);
            }
            #pragma unroll
            for (int nb = 0; nb < 8; ++nb) {
                int n = ncol + nb * 8 + g;
                uint32_t b0 = rnd(uB[(ko + tig) * BPITCH + n]);
                uint32_t b1 = rnd(uB[(ko + tig + 4) * BPITCH + n]);
                mma_tf32(acc[0][nb], a[0][0], a[0][1], a[0][2], a[0][3], b0, b1);
                mma_tf32(acc[1][nb], a[1][0], a[1][1], a[1][2], a[1][3], b0, b1);
            }
        }
        __syncthreads();
    }

    // ---- stage raw C into sC ----
    float* sC = sh;
    #pragma unroll
    for (int mb = 0; mb < 2; ++mb) {
        #pragma unroll
        for (int nb = 0; nb < 8; ++nb) {
            int r = mrow + mb * 16 + g;
            int cc = ncol + nb * 8 + 2 * tig;
            sC[r * CPITCH + cc]            = acc[mb][nb][0];
            sC[r * CPITCH + cc + 1]        = acc[mb][nb][1];
            sC[(r + 8) * CPITCH + cc]      = acc[mb][nb][2];
            sC[(r + 8) * CPITCH + cc + 1]  = acc[mb][nb][3];
        }
    }
    __syncthreads();

    // ---- mess pass: m = mk*C + com; write gmem + write back to sC ----
    for (int rr = 0; rr < 16; ++rr) {
        int r = wid * 16 + rr;
        int n = n0 + r;
        if (n >= N_NODES) break;
        float mk = sMask[r];
        float4 cv = *(const float4*)&sC[r * CPITCH + lane * 4];
        float4 cm = ((const float4*)com)[(size_t)n * 32 + lane];
        float4 m;
        m.x = fmaf(mk, cv.x, cm.x);
        m.y = fmaf(mk, cv.y, cm.y);
        m.z = fmaf(mk, cv.z, cm.z);
        m.w = fmaf(mk, cv.w, cm.w);
        ((float4*)(g_mess + ((size_t)t * N_NODES + n) * COM_DIM))[lane] = m;
        *(float4*)&sC[r * CPITCH + lane * 4] = m;
    }
    __syncthreads();

    // ---- el/er dots: lane = (row_sub, head); no shuffles ----
    {
        const int r_sub = lane >> 3, v = lane & 7;
        #pragma unroll
        for (int it = 0; it < 4; ++it) {
            int r = wid * 16 + it * 4 + r_sub;
            int n = n0 + r;
            const float4* mrow4 = (const float4*)&sC[r * CPITCH];
            const float4* arow4 = (const float4*)&sAttn[v * CPITCH];
            float dot = 0.f;
            #pragma unroll
            for (int k4 = 0; k4 < 32; ++k4) {
                float4 mv = mrow4[k4];
                float4 av = arow4[k4];
                dot = fmaf(mv.x, av.x, dot);
                dot = fmaf(mv.y, av.y, dot);
                dot = fmaf(mv.z, av.z, dot);
                dot = fmaf(mv.w, av.w, dot);
            }
            if (n < N_NODES) {
                if (v < 4) g_el[(size_t)n * ELSTRIDE + v * N_ETYPE + t] = dot;
                else       g_er[(size_t)n * ELSTRIDE + (v - 4) * N_ETYPE + t] = dot;
            }
        }
    }
}

// ---------------- CSR build ----------------
__global__ void zero_kernel() {
    int i = blockIdx.x * blockDim.x + threadIdx.x;
    if (i < N_NODES) g_deg[i] = 0;
}
__global__ void hist_kernel(const int* __restrict__ dst) {
    int m = blockIdx.x * blockDim.x + threadIdx.x;
    if (m < N_EDGES) atomicAdd(&g_deg[dst[m]], 1);
}
__global__ __launch_bounds__(1024) void scanA_kernel() {
    __shared__ int wsum[32];
    const int tid = threadIdx.x, lane = tid & 31, wid = tid >> 5;
    int idx = blockIdx.x * 1024 + tid;
    int v = (idx < N_NODES) ? g_deg[idx] : 0;
    int x = v;
    #pragma unroll
    for (int off = 1; off < 32; off <<= 1) {
        int y = __shfl_up_sync(0xffffffffu, x, off);
        if (lane >= off) x += y;
    }
    if (lane == 31) wsum[wid] = x;
    __syncthreads();
    if (wid == 0) {
        int s = wsum[lane];
        #pragma unroll
        for (int off = 1; off < 32; off <<= 1) {
            int y = __shfl_up_sync(0xffffffffu, s, off);
            if (lane >= off) s += y;
        }
        wsum[lane] = s;
        if (lane == 31) g_bsum[blockIdx.x] = s;
    }
    __syncthreads();
    int excl = (x - v) + (wid > 0 ? wsum[wid - 1] : 0);
    if (idx < N_NODES) g_rowptr[idx] = excl;
}
__global__ void scanB_kernel() {
    int lane = threadIdx.x;
    int v = (lane < SCAN_BLK) ? g_bsum[lane] : 0;
    int x = v;
    #pragma unroll
    for (int off = 1; off < 32; off <<= 1) {
        int y = __shfl_up_sync(0xffffffffu, x, off);
        if (lane >= off) x += y;
    }
    __shared__ int tot32;
    if (lane == 31) tot32 = x;
    __syncwarp();
    g_boff[lane] = x - v;
    if (lane == 0) {
        int run = tot32;
        for (int b = 32; b < SCAN_BLK; ++b) {
            g_boff[b] = run;
            run += g_bsum[b];
        }
        g_rowptr[N_NODES] = N_EDGES;
    }
}
__global__ void scanC_kernel() {
    int i = blockIdx.x * blockDim.x + threadIdx.x;
    if (i < N_NODES) {
        int r = g_rowptr[i] + g_boff[i >> 10];
        g_rowptr[i] = r;
        g_deg[i] = r;
    }
}
__global__ void scatter_kernel(const int* __restrict__ dst) {
    int m = blockIdx.x * blockDim.x + threadIdx.x;
    if (m < N_EDGES) {
        int pos = atomicAdd(&g_deg[dst[m]], 1);
        g_eidx[pos] = m;
    }
}

// ---------------- Phase 3: softmax + aggregate + ELU (warp per dst) ----------------
__global__ __launch_bounds__(256) void agg_kernel(
    const int* __restrict__ src, const int* __restrict__ etype,
    float* __restrict__ out)
{
    int warp = (blockIdx.x * blockDim.x + threadIdx.x) >> 5;
    if (warp >= N_NODES) return;
    const int lane = threadIdx.x & 31;
    const int d = warp;
    const int beg = g_rowptr[d], end = g_rowptr[d + 1];

    float er_ch = g_er[(size_t)d * ELSTRIDE + lane];

    float den = 0.f;
    for (int base = beg; base < end; base += 32) {
        int cnt = min(32, end - base);
        int s = 0, tt = 0;
        if (lane < cnt) {
            int m = g_eidx[base + lane];
            s = src[m];
            tt = etype[m];
        }
        for (int p = 0; p < cnt; ++p) {
            int sp = __shfl_sync(0xffffffffu, s, p);
            int tp = __shfl_sync(0xffffffffu, tt, p);
            float v = g_el[(size_t)sp * ELSTRIDE + lane] + er_ch;
            v = v >= 0.f ? v : NEG_SLOPE * v;
            float e = __expf(v);
            if (lane < NCH) {
                den += e;
                if (lane - (lane / N_ETYPE) * N_ETYPE == tp)
                    g_enum[(size_t)(base + p) * 4 + lane / N_ETYPE] = e;
            }
        }
    }
    float inv_den = (lane < NCH && den > 0.f) ? 1.f / den : 0.f;
    __threadfence_block();
    __syncwarp();

    float4 acc = make_float4(0.f, 0.f, 0.f, 0.f);
    for (int base = beg; base < end; base += 32) {
        int cnt = min(32, end - base);
        int s = 0, tt = 0;
        float4 en = make_float4(0.f, 0.f, 0.f, 0.f);
        if (lane < cnt) {
            int m = g_eidx[base + lane];
            s = src[m];
            tt = etype[m];
            en = ((const float4*)g_enum)[base + lane];
        }
        float id0 = __shfl_sync(0xffffffffu, inv_den, tt);
        float id1 = __shfl_sync(0xffffffffu, inv_den, tt + 5);
        float id2 = __shfl_sync(0xffffffffu, inv_den, tt + 10);
        float id3 = __shfl_sync(0xffffffffu, inv_den, tt + 15);
        float cp = en.x * id0 + en.y * id1 + en.z * id2 + en.w * id3;
        for (int p = 0; p < cnt; ++p) {
            int sp = __shfl_sync(0xffffffffu, s, p);
            int tp = __shfl_sync(0xffffffffu, tt, p);
            float c = __shfl_sync(0xffffffffu, cp, p);
            float4 mv = ((const float4*)g_mess)[((size_t)tp * N_NODES + sp) * 32 + lane];
            acc.x = fmaf(c, mv.x, acc.x);
            acc.y = fmaf(c, mv.y, acc.y);
            acc.z = fmaf(c, mv.z, acc.z);
            acc.w = fmaf(c, mv.w, acc.w);
        }
    }
    float4 o;
    o.x = acc.x > 0.f ? acc.x : expm1f(acc.x);
    o.y = acc.y > 0.f ? acc.y : expm1f(acc.y);
    o.z = acc.z > 0.f ? acc.z : expm1f(acc.z);
    o.w = acc.w > 0.f ? acc.w : expm1f(acc.w);
    ((float4*)out)[(size_t)d * 32 + lane] = o;
}

// ---------------- launch ----------------
extern "C" void kernel_launch(void* const* d_in, const int* in_sizes, int n_in,
                              void* d_out, int out_size)
{
    const float* feat   = (const float*)d_in[0];
    const float* com    = (const float*)d_in[1];
    const float* mask   = (const float*)d_in[2];
    const float* W      = (const float*)d_in[3];
    const float* attn_l = (const float*)d_in[4];
    const float* attn_r = (const float*)d_in[5];
    const int*   src    = (const int*)d_in[6];
    const int*   dst    = (const int*)d_in[7];
    const int*   etype  = (const int*)d_in[8];
    float* out = (float*)d_out;

    const int smem = SH_WORDS * (int)sizeof(float);   // 71680 B
    cudaFuncSetAttribute(mma_kernel, cudaFuncAttributeMaxDynamicSharedMemorySize, smem);

    // mma_kernel kept at launch index 3 (ncu capture slot)
    zero_kernel<<<(N_NODES + 255) / 256, 256>>>();
    hist_kernel<<<(N_EDGES + 255) / 256, 256>>>(dst);
    scanA_kernel<<<SCAN_BLK, 1024>>>();
    mma_kernel<<<dim3(NTILES, N_ETYPE), 256, smem>>>(feat, com, mask, W, attn_l, attn_r);
    scanB_kernel<<<1, 32>>>();
    scanC_kernel<<<(N_NODES + 255) / 256, 256>>>();
    scatter_kernel<<<(N_EDGES + 255) / 256, 256>>>(dst);
    agg_kernel<<<(N_NODES * 32 + 255) / 256, 256>>>(src, etype, out);
}